// round 15
// baseline (speedup 1.0000x reference)
#include <cuda_runtime.h>

// WaveletAttention: 3-level Haar DWT -> per-batch scalar gates -> gated IDWT.
// R15: k_forward = R11's weight-sharing decomposition (CTA = 8 warps = 8
// batches over one spatial tile -> weight loads dedupe in the CTA's L1,
// weight LTS traffic 99MB -> ~25MB) + R9's NON-ATOMIC reduction (per-warp
// shfl reduce -> per-CTA g_part slot -> last-CTA-per-octet final reduce).
// R11's failure was the atomicAdd serialization, not the sharing.
// k_recon = R14 verbatim (19.55us measured).

#define HH 1024
#define WW 1024
#define NB 16
#define N1c 262144   // 512*512 per component, weights Wd3 (finest)
#define N2c 65536    // 256*256, weights Wd2
#define N3c 16384    // 128*128, weights Wd1 (coarsest)
#define SPATIAL 1024   // 8 col-chunks x 128 row-groups per octet

// partials: [octet][8 batches x 10 logits = 80 rows][SPATIAL]
__device__ float g_part[2 * 80 * SPATIAL];
__device__ float g_gates[NB * 10];
__device__ unsigned int g_cnt[2];   // per octet, wraps via atomicInc

__device__ __forceinline__ void haar_fwd(float x00, float x01, float x10, float x11,
                                         float& a, float& h, float& v, float& dd) {
    float s0 = x00 + x01, m0 = x00 - x01;
    float s1 = x10 + x11, m1 = x10 - x11;
    a  = 0.5f * (s0 + s1);
    h  = 0.5f * (s0 - s1);
    v  = 0.5f * (m0 + m1);
    dd = 0.5f * (m0 - m1);
}

__device__ __forceinline__ void haar_inv(float a, float h, float v, float dd,
                                         float& x00, float& x01, float& x10, float& x11) {
    float ph = a + h, mh = a - h;
    float pv = v + dd, mv = v - dd;
    x00 = 0.5f * (ph + pv);
    x01 = 0.5f * (ph - pv);
    x10 = 0.5f * (mh + mv);
    x11 = 0.5f * (mh - mv);
}

__device__ __forceinline__ void softmax3g(float l0, float l1, float l2, float* out) {
    float m = fmaxf(fmaxf(l0, l1), l2);
    float e0 = __expf(l0 - m), e1 = __expf(l1 - m), e2 = __expf(l2 - m);
    float inv = 1.0f / (e0 + e1 + e2);
    out[0] = e0 * inv; out[1] = e1 * inv; out[2] = e2 * inv;
}

// ---------------------------------------------------------------------------
// K1: forward DWT + logits. CTA = 8 warps = 8 batches (one octet) over one
// spatial tile (32 col-groups x 8 rows). Weight addresses identical across
// the 8 warps -> L1 dedupe. Per-warp reduce -> per-CTA g_part slot (no
// atomics). Last CTA per octet reduces 80x1024 partials -> gates.
// grid: (SPATIAL, 2) x 256.
// ---------------------------------------------------------------------------
__global__ void __launch_bounds__(256) k_forward(
    const float* __restrict__ x,
    const float* __restrict__ Wa,
    const float* __restrict__ Wd1,
    const float* __restrict__ Wd2,
    const float* __restrict__ Wd3,
    const float* __restrict__ ba,
    const float* __restrict__ bd1,
    const float* __restrict__ bd2,
    const float* __restrict__ bd3)
{
    const int octet = blockIdx.y;                 // 0..1
    const int cc = blockIdx.x & 7;                // col chunk (32 col-groups)
    const int r  = blockIdx.x >> 3;               // row group (8 rows)
    const int lane = threadIdx.x & 31;
    const int wslot = threadIdx.x >> 5;           // 0..7 = batch slot
    const int batch = octet * 8 + wslot;
    const int g = cc * 32 + lane;                 // col group (4 cols)

    const float* xb = x + (size_t)batch * (HH * WW) + (size_t)(r * 8) * WW + g * 4;

    float sa = 0.f, s1x = 0.f, s1y = 0.f, s1z = 0.f;
    float s2x = 0.f, s2y = 0.f, s2z = 0.f, s3x = 0.f, s3y = 0.f, s3z = 0.f;
    float a0[4], a1[4];

    // ---- level 1 ----
    #pragma unroll
    for (int ry = 0; ry < 4; ry++) {
        float4 u = *(const float4*)(xb + (size_t)(2 * ry) * WW);
        float4 w = *(const float4*)(xb + (size_t)(2 * ry + 1) * WW);

        const size_t i = (size_t)(r * 4 + ry) * 512 + 2 * g;   // even
        const float* ph = Wd3 + 3 * i;
        const float* pv = Wd3 + 3 * (N1c + i);
        const float* pd = Wd3 + 3 * (2 * (size_t)N1c + i);
        float2 ha = *(const float2*)(ph), hb = *(const float2*)(ph + 2), hc = *(const float2*)(ph + 4);
        float2 va = *(const float2*)(pv), vb = *(const float2*)(pv + 2), vc = *(const float2*)(pv + 4);
        float2 da = *(const float2*)(pd), db = *(const float2*)(pd + 2), dc = *(const float2*)(pd + 4);

        float h0, v0, d0, h1, v1, d1;
        haar_fwd(u.x, u.y, w.x, w.y, a0[ry], h0, v0, d0);
        haar_fwd(u.z, u.w, w.z, w.w, a1[ry], h1, v1, d1);
        s1x += h0 * ha.x + h1 * hb.y + v0 * va.x + v1 * vb.y + d0 * da.x + d1 * db.y;
        s1y += h0 * ha.y + h1 * hc.x + v0 * va.y + v1 * vc.x + d0 * da.y + d1 * dc.x;
        s1z += h0 * hb.x + h1 * hc.y + v0 * vb.x + v1 * vc.y + d0 * db.x + d1 * dc.y;
    }

    // ---- level 2 ----
    float a2[2];
    #pragma unroll
    for (int ry2 = 0; ry2 < 2; ry2++) {
        const size_t i = (size_t)(r * 2 + ry2) * 256 + g;
        const float* ph = Wd2 + 3 * i;
        const float* pv = Wd2 + 3 * (N2c + i);
        const float* pd = Wd2 + 3 * (2 * (size_t)N2c + i);
        float w0 = __ldg(ph + 0), w1 = __ldg(ph + 1), w2 = __ldg(ph + 2);
        float w3 = __ldg(pv + 0), w4 = __ldg(pv + 1), w5 = __ldg(pv + 2);
        float w6 = __ldg(pd + 0), w7 = __ldg(pd + 1), w8 = __ldg(pd + 2);

        float h, v, dd;
        haar_fwd(a0[2*ry2], a1[2*ry2], a0[2*ry2+1], a1[2*ry2+1], a2[ry2], h, v, dd);
        s2x += h * w0 + v * w3 + dd * w6;
        s2y += h * w1 + v * w4 + dd * w7;
        s2z += h * w2 + v * w5 + dd * w8;
    }

    // ---- level 3: lane pairs ----
    {
        float pa0 = __shfl_xor_sync(0xFFFFFFFFu, a2[0], 1);
        float pa1 = __shfl_xor_sync(0xFFFFFFFFu, a2[1], 1);
        if ((g & 1) == 0) {
            const size_t i = (size_t)r * 128 + (g >> 1);
            const float* ph = Wd1 + 3 * i;
            const float* pv = Wd1 + 3 * (N3c + i);
            const float* pd = Wd1 + 3 * (2 * (size_t)N3c + i);
            float w0 = __ldg(ph + 0), w1 = __ldg(ph + 1), w2 = __ldg(ph + 2);
            float w3 = __ldg(pv + 0), w4 = __ldg(pv + 1), w5 = __ldg(pv + 2);
            float w6 = __ldg(pd + 0), w7 = __ldg(pd + 1), w8 = __ldg(pd + 2);

            float a, h, v, dd;
            haar_fwd(a2[0], pa0, a2[1], pa1, a, h, v, dd);
            s3x = h * w0 + v * w3 + dd * w6;
            s3y = h * w1 + v * w4 + dd * w7;
            s3z = h * w2 + v * w5 + dd * w8;
            sa  = a * __ldg(Wa + i);
        }
    }

    // ---- per-warp reduce of 10 scalars; lane0 writes per-CTA slot ----
    float vals[10] = {sa, s3x, s3y, s3z, s2x, s2y, s2z, s1x, s1y, s1z};
    #pragma unroll
    for (int k = 0; k < 10; k++) {
        float v = vals[k];
        #pragma unroll
        for (int o = 16; o > 0; o >>= 1)
            v += __shfl_down_sync(0xFFFFFFFFu, v, o);
        vals[k] = v;
    }
    if (lane == 0) {
        float* p = g_part + ((size_t)(octet * 80 + wslot * 10)) * SPATIAL + blockIdx.x;
        #pragma unroll
        for (int k = 0; k < 10; k++) p[(size_t)k * SPATIAL] = vals[k];
    }

    // ---- last CTA of this octet: final reduce -> gates ----
    __shared__ bool isLast;
    __threadfence();
    __syncthreads();
    if (threadIdx.x == 0) {
        unsigned int old = atomicInc(&g_cnt[octet], SPATIAL - 1);   // wraps to 0
        isLast = (old == SPATIAL - 1);
    }
    __syncthreads();
    if (!isLast) return;

    __shared__ float red[80];
    const int wid = threadIdx.x >> 5;
    for (int row = wid; row < 80; row += 8) {
        const float4* p = (const float4*)(g_part + (size_t)(octet * 80 + row) * SPATIAL);
        float s = 0.f;
        #pragma unroll
        for (int j = 0; j < SPATIAL / 4 / 32; j++) {
            float4 v = p[lane + j * 32];
            s += (v.x + v.y) + (v.z + v.w);
        }
        #pragma unroll
        for (int o = 16; o > 0; o >>= 1)
            s += __shfl_down_sync(0xFFFFFFFFu, s, o);
        if (lane == 0) red[row] = s;
    }
    __syncthreads();
    if (threadIdx.x < 8) {
        const float* L = red + threadIdx.x * 10;
        float* G = g_gates + (octet * 8 + threadIdx.x) * 10;
        G[0] = 1.0f / (1.0f + __expf(-(L[0] + ba[0])));
        softmax3g(L[1] + bd1[0], L[2] + bd1[1], L[3] + bd1[2], G + 1);
        softmax3g(L[4] + bd2[0], L[5] + bd2[1], L[6] + bd2[2], G + 4);
        softmax3g(L[7] + bd3[0], L[8] + bd3[1], L[9] + bd3[2], G + 7);
    }
}

// ---------------------------------------------------------------------------
// K2: single-pass reconstruct (R14 verbatim; 19.55us measured).
// grid: (128, NB) x 256.
// ---------------------------------------------------------------------------
__global__ void __launch_bounds__(256, 5) k_recon(
    const float* __restrict__ x, float* __restrict__ out)
{
    const int batch = blockIdx.y;
    const int bt = blockIdx.x * blockDim.x + threadIdx.x;
    const int g = bt & 255;
    const int r = bt >> 8;
    const size_t base = (size_t)batch * (HH * WW) + (size_t)(r * 8) * WW + g * 4;
    const float* xb = x + base;
    float* ob = out + base;

    // ---- front-batch ALL 8 row loads ----
    float4 u[4], w[4];
    #pragma unroll
    for (int ry = 0; ry < 4; ry++) {
        u[ry] = *(const float4*)(xb + (size_t)(2 * ry) * WW);
        w[ry] = *(const float4*)(xb + (size_t)(2 * ry + 1) * WW);
    }

    const float* G = g_gates + batch * 10;
    const float aw  = __ldg(G + 0);
    const float g3h = __ldg(G + 1), g3v = __ldg(G + 2), g3d = __ldg(G + 3);
    const float g2h = __ldg(G + 4), g2v = __ldg(G + 5), g2d = __ldg(G + 6);
    const float g1h = __ldg(G + 7), g1v = __ldg(G + 8), g1d = __ldg(G + 9);

    // ---- forward level 1 (store gated details) ----
    float a1_0[4], a1_1[4];
    float h1_0[4], v1_0[4], d1_0[4];
    float h1_1[4], v1_1[4], d1_1[4];
    #pragma unroll
    for (int ry = 0; ry < 4; ry++) {
        float h, v, dd;
        haar_fwd(u[ry].x, u[ry].y, w[ry].x, w[ry].y, a1_0[ry], h, v, dd);
        h1_0[ry] = h * g1h; v1_0[ry] = v * g1v; d1_0[ry] = dd * g1d;
        haar_fwd(u[ry].z, u[ry].w, w[ry].z, w[ry].w, a1_1[ry], h, v, dd);
        h1_1[ry] = h * g1h; v1_1[ry] = v * g1v; d1_1[ry] = dd * g1d;
    }

    // ---- forward level 2 (gated) ----
    float a2[2], h2[2], v2[2], d2[2];
    #pragma unroll
    for (int ry2 = 0; ry2 < 2; ry2++) {
        float h, v, dd;
        haar_fwd(a1_0[2*ry2], a1_1[2*ry2], a1_0[2*ry2+1], a1_1[2*ry2+1],
                 a2[ry2], h, v, dd);
        h2[ry2] = h * g2h; v2[ry2] = v * g2v; d2[ry2] = dd * g2d;
    }

    // ---- level 3: symmetric in both lanes of the pair ----
    float R2[2];
    {
        float pa0 = __shfl_xor_sync(0xFFFFFFFFu, a2[0], 1);
        float pa1 = __shfl_xor_sync(0xFFFFFFFFu, a2[1], 1);
        bool odd = (g & 1);
        float lo0 = odd ? pa0 : a2[0], hi0 = odd ? a2[0] : pa0;
        float lo1 = odd ? pa1 : a2[1], hi1 = odd ? a2[1] : pa1;
        float a, h, v, dd;
        haar_fwd(lo0, hi0, lo1, hi1, a, h, v, dd);
        a *= aw; h *= g3h; v *= g3v; dd *= g3d;
        float x00, x01, x10, x11;
        haar_inv(a, h, v, dd, x00, x01, x10, x11);
        R2[0] = odd ? x01 : x00;
        R2[1] = odd ? x11 : x10;
    }

    // ---- inverse level 2 ----
    float r1_0[4], r1_1[4];
    #pragma unroll
    for (int ry2 = 0; ry2 < 2; ry2++) {
        haar_inv(R2[ry2], h2[ry2], v2[ry2], d2[ry2],
                 r1_0[2*ry2], r1_1[2*ry2], r1_0[2*ry2+1], r1_1[2*ry2+1]);
    }

    // ---- inverse level 1 + coalesced float4 stores ----
    #pragma unroll
    for (int ry = 0; ry < 4; ry++) {
        float p00, p01, p10, p11, q00, q01, q10, q11;
        haar_inv(r1_0[ry], h1_0[ry], v1_0[ry], d1_0[ry], p00, p01, p10, p11);
        haar_inv(r1_1[ry], h1_1[ry], v1_1[ry], d1_1[ry], q00, q01, q10, q11);
        *(float4*)(ob + (size_t)(2 * ry) * WW)     = make_float4(p00, p01, q00, q01);
        *(float4*)(ob + (size_t)(2 * ry + 1) * WW) = make_float4(p10, p11, q10, q11);
    }
}

// ---------------------------------------------------------------------------
extern "C" void kernel_launch(void* const* d_in, const int* in_sizes, int n_in,
                              void* d_out, int out_size) {
    const float* x   = (const float*)d_in[0];
    const float* Wa  = (const float*)d_in[1];
    const float* ba  = (const float*)d_in[2];
    const float* Wd1 = (const float*)d_in[3];
    const float* bd1 = (const float*)d_in[4];
    const float* Wd2 = (const float*)d_in[5];
    const float* bd2 = (const float*)d_in[6];
    const float* Wd3 = (const float*)d_in[7];
    const float* bd3 = (const float*)d_in[8];
    float* out = (float*)d_out;

    k_forward<<<dim3(SPATIAL, 2), 256>>>(x, Wa, Wd1, Wd2, Wd3,
                                         ba, bd1, bd2, bd3);
    k_recon<<<dim3(128, NB), 256>>>(x, out);
}

// round 16
// speedup vs baseline: 1.1527x; 1.1527x over previous
#include <cuda_runtime.h>

// WaveletAttention: 3-level Haar DWT -> per-batch scalar gates -> gated IDWT.
// R16: R9/R14 base (proven 47.8us x3). Single change: k_forward occupancy.
//   - level-2 interleaved into the level-1 row-pair loop: live 'a' arrays
//     16 -> 8 regs, level-2 weight loads issued mid-kernel (latency overlap)
//   - __launch_bounds__(256,5): 5 CTAs/SM (+25% warps) with minimal spill
// k_recon = R14 verbatim (19.55us measured, untouched).

#define HH 1024
#define WW 1024
#define NB 16
#define N1c 262144   // 512*512 per component, weights Wd3 (finest)
#define N2c 65536    // 256*256, weights Wd2
#define N3c 16384    // 128*128, weights Wd1 (coarsest)
#define FWD_BLOCKS 128

// partials: [pair][20][FWD_BLOCKS]
__device__ float g_part[(NB / 2) * 20 * FWD_BLOCKS];
__device__ float g_gates[NB * 10];
__device__ unsigned int g_cnt[NB / 2];   // wraps via atomicInc

__device__ __forceinline__ void haar_fwd(float x00, float x01, float x10, float x11,
                                         float& a, float& h, float& v, float& dd) {
    float s0 = x00 + x01, m0 = x00 - x01;
    float s1 = x10 + x11, m1 = x10 - x11;
    a  = 0.5f * (s0 + s1);
    h  = 0.5f * (s0 - s1);
    v  = 0.5f * (m0 + m1);
    dd = 0.5f * (m0 - m1);
}

__device__ __forceinline__ void haar_inv(float a, float h, float v, float dd,
                                         float& x00, float& x01, float& x10, float& x11) {
    float ph = a + h, mh = a - h;
    float pv = v + dd, mv = v - dd;
    x00 = 0.5f * (ph + pv);
    x01 = 0.5f * (ph - pv);
    x10 = 0.5f * (mh + mv);
    x11 = 0.5f * (mh - mv);
}

__device__ __forceinline__ void softmax3g(float l0, float l1, float l2, float* out) {
    float m = fmaxf(fmaxf(l0, l1), l2);
    float e0 = __expf(l0 - m), e1 = __expf(l1 - m), e2 = __expf(l2 - m);
    float inv = 1.0f / (e0 + e1 + e2);
    out[0] = e0 * inv; out[1] = e1 * inv; out[2] = e2 * inv;
}

// ---------------------------------------------------------------------------
// K1: forward DWT + logit partials + last-CTA gate finalization.
// Level 2 interleaved per row-pair to shrink live registers.
// grid: (FWD_BLOCKS, NB/2) x 256.
// ---------------------------------------------------------------------------
__global__ void __launch_bounds__(256, 5) k_forward(
    const float* __restrict__ x,
    const float* __restrict__ Wa,
    const float* __restrict__ Wd1,
    const float* __restrict__ Wd2,
    const float* __restrict__ Wd3,
    const float* __restrict__ ba,
    const float* __restrict__ bd1,
    const float* __restrict__ bd2,
    const float* __restrict__ bd3)
{
    const int b0 = blockIdx.y * 2;
    const int bt = blockIdx.x * blockDim.x + threadIdx.x;
    const int g = bt & 255;
    const int r = bt >> 8;
    const size_t off = (size_t)(r * 8) * WW + g * 4;
    const float* xA = x + (size_t)b0 * (HH * WW) + off;
    const float* xB = xA + (size_t)(HH * WW);

    float saA = 0.f, s1xA = 0.f, s1yA = 0.f, s1zA = 0.f;
    float s2xA = 0.f, s2yA = 0.f, s2zA = 0.f, s3xA = 0.f, s3yA = 0.f, s3zA = 0.f;
    float saB = 0.f, s1xB = 0.f, s1yB = 0.f, s1zB = 0.f;
    float s2xB = 0.f, s2yB = 0.f, s2zB = 0.f, s3xB = 0.f, s3yB = 0.f, s3zB = 0.f;

    float a2A[2], a2B[2];

    // ---- levels 1+2 interleaved per row-pair (ry2 = L2 row) ----
    #pragma unroll
    for (int ry2 = 0; ry2 < 2; ry2++) {
        float aA[2][2], aB[2][2];   // [row-in-pair][L1 col], freed each ry2

        #pragma unroll
        for (int hh = 0; hh < 2; hh++) {
            const int ry = 2 * ry2 + hh;
            float4 uA = *(const float4*)(xA + (size_t)(2 * ry) * WW);
            float4 wA = *(const float4*)(xA + (size_t)(2 * ry + 1) * WW);
            float4 uB = *(const float4*)(xB + (size_t)(2 * ry) * WW);
            float4 wB = *(const float4*)(xB + (size_t)(2 * ry + 1) * WW);

            const size_t i = (size_t)(r * 4 + ry) * 512 + 2 * g;
            const float* ph = Wd3 + 3 * i;
            const float* pv = Wd3 + 3 * (N1c + i);
            const float* pd = Wd3 + 3 * (2 * (size_t)N1c + i);
            float2 ha = *(const float2*)(ph), hb = *(const float2*)(ph + 2), hc = *(const float2*)(ph + 4);
            float2 va = *(const float2*)(pv), vb = *(const float2*)(pv + 2), vc = *(const float2*)(pv + 4);
            float2 da = *(const float2*)(pd), db = *(const float2*)(pd + 2), dc = *(const float2*)(pd + 4);

            float h0, v0, d0, h1, v1, d1;
            haar_fwd(uA.x, uA.y, wA.x, wA.y, aA[hh][0], h0, v0, d0);
            haar_fwd(uA.z, uA.w, wA.z, wA.w, aA[hh][1], h1, v1, d1);
            s1xA += h0 * ha.x + h1 * hb.y + v0 * va.x + v1 * vb.y + d0 * da.x + d1 * db.y;
            s1yA += h0 * ha.y + h1 * hc.x + v0 * va.y + v1 * vc.x + d0 * da.y + d1 * dc.x;
            s1zA += h0 * hb.x + h1 * hc.y + v0 * vb.x + v1 * vc.y + d0 * db.x + d1 * dc.y;

            haar_fwd(uB.x, uB.y, wB.x, wB.y, aB[hh][0], h0, v0, d0);
            haar_fwd(uB.z, uB.w, wB.z, wB.w, aB[hh][1], h1, v1, d1);
            s1xB += h0 * ha.x + h1 * hb.y + v0 * va.x + v1 * vb.y + d0 * da.x + d1 * db.y;
            s1yB += h0 * ha.y + h1 * hc.x + v0 * va.y + v1 * vc.x + d0 * da.y + d1 * dc.x;
            s1zB += h0 * hb.x + h1 * hc.y + v0 * vb.x + v1 * vc.y + d0 * db.x + d1 * dc.y;
        }

        // ---- level 2 for this row-pair ----
        {
            const size_t i = (size_t)(r * 2 + ry2) * 256 + g;
            const float* ph = Wd2 + 3 * i;
            const float* pv = Wd2 + 3 * (N2c + i);
            const float* pd = Wd2 + 3 * (2 * (size_t)N2c + i);
            float w0 = __ldg(ph + 0), w1 = __ldg(ph + 1), w2 = __ldg(ph + 2);
            float w3 = __ldg(pv + 0), w4 = __ldg(pv + 1), w5 = __ldg(pv + 2);
            float w6 = __ldg(pd + 0), w7 = __ldg(pd + 1), w8 = __ldg(pd + 2);

            float h, v, dd;
            haar_fwd(aA[0][0], aA[0][1], aA[1][0], aA[1][1], a2A[ry2], h, v, dd);
            s2xA += h * w0 + v * w3 + dd * w6;
            s2yA += h * w1 + v * w4 + dd * w7;
            s2zA += h * w2 + v * w5 + dd * w8;

            haar_fwd(aB[0][0], aB[0][1], aB[1][0], aB[1][1], a2B[ry2], h, v, dd);
            s2xB += h * w0 + v * w3 + dd * w6;
            s2yB += h * w1 + v * w4 + dd * w7;
            s2zB += h * w2 + v * w5 + dd * w8;
        }
    }

    // ---- level 3: combine lane pairs; only even lane accumulates ----
    {
        float pA0 = __shfl_xor_sync(0xFFFFFFFFu, a2A[0], 1);
        float pA1 = __shfl_xor_sync(0xFFFFFFFFu, a2A[1], 1);
        float pB0 = __shfl_xor_sync(0xFFFFFFFFu, a2B[0], 1);
        float pB1 = __shfl_xor_sync(0xFFFFFFFFu, a2B[1], 1);
        if ((g & 1) == 0) {
            const size_t i = (size_t)r * 128 + (g >> 1);
            const float* ph = Wd1 + 3 * i;
            const float* pv = Wd1 + 3 * (N3c + i);
            const float* pd = Wd1 + 3 * (2 * (size_t)N3c + i);
            float w0 = __ldg(ph + 0), w1 = __ldg(ph + 1), w2 = __ldg(ph + 2);
            float w3 = __ldg(pv + 0), w4 = __ldg(pv + 1), w5 = __ldg(pv + 2);
            float w6 = __ldg(pd + 0), w7 = __ldg(pd + 1), w8 = __ldg(pd + 2);
            float wa = __ldg(Wa + i);

            float a, h, v, dd;
            haar_fwd(a2A[0], pA0, a2A[1], pA1, a, h, v, dd);
            s3xA = h * w0 + v * w3 + dd * w6;
            s3yA = h * w1 + v * w4 + dd * w7;
            s3zA = h * w2 + v * w5 + dd * w8;
            saA  = a * wa;

            haar_fwd(a2B[0], pB0, a2B[1], pB1, a, h, v, dd);
            s3xB = h * w0 + v * w3 + dd * w6;
            s3yB = h * w1 + v * w4 + dd * w7;
            s3zB = h * w2 + v * w5 + dd * w8;
            saB  = a * wa;
        }
    }

    // ---- block reduction of 20 scalars -> per-CTA partials ----
    float vals[20] = {saA, s3xA, s3yA, s3zA, s2xA, s2yA, s2zA, s1xA, s1yA, s1zA,
                      saB, s3xB, s3yB, s3zB, s2xB, s2yB, s2zB, s1xB, s1yB, s1zB};
    __shared__ float sm[20][8];
    int lane = threadIdx.x & 31;
    int wid  = threadIdx.x >> 5;
    #pragma unroll
    for (int k = 0; k < 20; k++) {
        float v = vals[k];
        #pragma unroll
        for (int off2 = 16; off2 > 0; off2 >>= 1)
            v += __shfl_down_sync(0xFFFFFFFFu, v, off2);
        if (lane == 0) sm[k][wid] = v;
    }
    __syncthreads();
    if (threadIdx.x < 20) {
        float t = 0.f;
        #pragma unroll
        for (int w = 0; w < 8; w++) t += sm[threadIdx.x][w];
        g_part[(blockIdx.y * 20 + threadIdx.x) * FWD_BLOCKS + blockIdx.x] = t;
    }

    // ---- last CTA of this pair: reduce partials -> gates ----
    __shared__ bool isLast;
    __syncthreads();
    __threadfence();
    if (threadIdx.x == 0) {
        unsigned int old = atomicInc(&g_cnt[blockIdx.y], FWD_BLOCKS - 1);
        isLast = (old == FWD_BLOCKS - 1);
    }
    __syncthreads();
    if (!isLast) return;

    __shared__ float red[20];
    for (int k = wid; k < 20; k += 8) {
        const float* p = g_part + (size_t)(blockIdx.y * 20 + k) * FWD_BLOCKS;
        float v = p[lane] + p[lane + 32] + p[lane + 64] + p[lane + 96];
        #pragma unroll
        for (int off2 = 16; off2 > 0; off2 >>= 1)
            v += __shfl_down_sync(0xFFFFFFFFu, v, off2);
        if (lane == 0) red[k] = v;
    }
    __syncthreads();
    if (threadIdx.x < 2) {
        const float* L = red + threadIdx.x * 10;
        float* G = g_gates + (b0 + threadIdx.x) * 10;
        G[0] = 1.0f / (1.0f + __expf(-(L[0] + ba[0])));
        softmax3g(L[1] + bd1[0], L[2] + bd1[1], L[3] + bd1[2], G + 1);
        softmax3g(L[4] + bd2[0], L[5] + bd2[1], L[6] + bd2[2], G + 4);
        softmax3g(L[7] + bd3[0], L[8] + bd3[1], L[9] + bd3[2], G + 7);
    }
}

// ---------------------------------------------------------------------------
// K2: single-pass reconstruct (R14 verbatim; 19.55us measured).
// grid: (128, NB) x 256.
// ---------------------------------------------------------------------------
__global__ void __launch_bounds__(256, 5) k_recon(
    const float* __restrict__ x, float* __restrict__ out)
{
    const int batch = blockIdx.y;
    const int bt = blockIdx.x * blockDim.x + threadIdx.x;
    const int g = bt & 255;
    const int r = bt >> 8;
    const size_t base = (size_t)batch * (HH * WW) + (size_t)(r * 8) * WW + g * 4;
    const float* xb = x + base;
    float* ob = out + base;

    // ---- front-batch ALL 8 row loads ----
    float4 u[4], w[4];
    #pragma unroll
    for (int ry = 0; ry < 4; ry++) {
        u[ry] = *(const float4*)(xb + (size_t)(2 * ry) * WW);
        w[ry] = *(const float4*)(xb + (size_t)(2 * ry + 1) * WW);
    }

    const float* G = g_gates + batch * 10;
    const float aw  = __ldg(G + 0);
    const float g3h = __ldg(G + 1), g3v = __ldg(G + 2), g3d = __ldg(G + 3);
    const float g2h = __ldg(G + 4), g2v = __ldg(G + 5), g2d = __ldg(G + 6);
    const float g1h = __ldg(G + 7), g1v = __ldg(G + 8), g1d = __ldg(G + 9);

    // ---- forward level 1 (store gated details) ----
    float a1_0[4], a1_1[4];
    float h1_0[4], v1_0[4], d1_0[4];
    float h1_1[4], v1_1[4], d1_1[4];
    #pragma unroll
    for (int ry = 0; ry < 4; ry++) {
        float h, v, dd;
        haar_fwd(u[ry].x, u[ry].y, w[ry].x, w[ry].y, a1_0[ry], h, v, dd);
        h1_0[ry] = h * g1h; v1_0[ry] = v * g1v; d1_0[ry] = dd * g1d;
        haar_fwd(u[ry].z, u[ry].w, w[ry].z, w[ry].w, a1_1[ry], h, v, dd);
        h1_1[ry] = h * g1h; v1_1[ry] = v * g1v; d1_1[ry] = dd * g1d;
    }

    // ---- forward level 2 (gated) ----
    float a2[2], h2[2], v2[2], d2[2];
    #pragma unroll
    for (int ry2 = 0; ry2 < 2; ry2++) {
        float h, v, dd;
        haar_fwd(a1_0[2*ry2], a1_1[2*ry2], a1_0[2*ry2+1], a1_1[2*ry2+1],
                 a2[ry2], h, v, dd);
        h2[ry2] = h * g2h; v2[ry2] = v * g2v; d2[ry2] = dd * g2d;
    }

    // ---- level 3: symmetric in both lanes of the pair ----
    float R2[2];
    {
        float pa0 = __shfl_xor_sync(0xFFFFFFFFu, a2[0], 1);
        float pa1 = __shfl_xor_sync(0xFFFFFFFFu, a2[1], 1);
        bool odd = (g & 1);
        float lo0 = odd ? pa0 : a2[0], hi0 = odd ? a2[0] : pa0;
        float lo1 = odd ? pa1 : a2[1], hi1 = odd ? a2[1] : pa1;
        float a, h, v, dd;
        haar_fwd(lo0, hi0, lo1, hi1, a, h, v, dd);
        a *= aw; h *= g3h; v *= g3v; dd *= g3d;
        float x00, x01, x10, x11;
        haar_inv(a, h, v, dd, x00, x01, x10, x11);
        R2[0] = odd ? x01 : x00;
        R2[1] = odd ? x11 : x10;
    }

    // ---- inverse level 2 ----
    float r1_0[4], r1_1[4];
    #pragma unroll
    for (int ry2 = 0; ry2 < 2; ry2++) {
        haar_inv(R2[ry2], h2[ry2], v2[ry2], d2[ry2],
                 r1_0[2*ry2], r1_1[2*ry2], r1_0[2*ry2+1], r1_1[2*ry2+1]);
    }

    // ---- inverse level 1 + coalesced float4 stores ----
    #pragma unroll
    for (int ry = 0; ry < 4; ry++) {
        float p00, p01, p10, p11, q00, q01, q10, q11;
        haar_inv(r1_0[ry], h1_0[ry], v1_0[ry], d1_0[ry], p00, p01, p10, p11);
        haar_inv(r1_1[ry], h1_1[ry], v1_1[ry], d1_1[ry], q00, q01, q10, q11);
        *(float4*)(ob + (size_t)(2 * ry) * WW)     = make_float4(p00, p01, q00, q01);
        *(float4*)(ob + (size_t)(2 * ry + 1) * WW) = make_float4(p10, p11, q10, q11);
    }
}

// ---------------------------------------------------------------------------
extern "C" void kernel_launch(void* const* d_in, const int* in_sizes, int n_in,
                              void* d_out, int out_size) {
    const float* x   = (const float*)d_in[0];
    const float* Wa  = (const float*)d_in[1];
    const float* ba  = (const float*)d_in[2];
    const float* Wd1 = (const float*)d_in[3];
    const float* bd1 = (const float*)d_in[4];
    const float* Wd2 = (const float*)d_in[5];
    const float* bd2 = (const float*)d_in[6];
    const float* Wd3 = (const float*)d_in[7];
    const float* bd3 = (const float*)d_in[8];
    float* out = (float*)d_out;

    k_forward<<<dim3(FWD_BLOCKS, NB / 2), 256>>>(x, Wa, Wd1, Wd2, Wd3,
                                                 ba, bd1, bd2, bd3);
    k_recon<<<dim3(128, NB), 256>>>(x, out);
}